// round 15
// baseline (speedup 1.0000x reference)
#include <cuda_runtime.h>

#define BB 16
#define SS 4096
#define HH 1024
#define QD 1024
#define KD 2048
#define SSPLIT 32
#define SCHUNK (SS / SSPLIT)   // 128

// Scratch (no allocation allowed anywhere)
__device__ float g_q[BB * HH];                 // 64 KB
__device__ float g_escore[BB * SS];            // 256 KB unnormalized exp(score)
__device__ float g_partial[SSPLIT * BB * KD];  // 4 MB unnormalized ctx partials
__device__ float g_csum[BB * SSPLIT];          // per-chunk escore sums

__device__ __forceinline__ float tanh_fast(float x) {
    float y;
    asm("tanh.approx.f32 %0, %1;" : "=f"(y) : "f"(x));
    return y;
}

// ---------------------------------------------------------------------------
// K1: q[b,h] = query[b,:]·Wq[h,:].  Warp per h-row, all 16 batches in regs.
// Wq read once (4 MB DRAM); query (64 KB) broadcast from L2. 1024 warps.
// ---------------------------------------------------------------------------
__global__ void __launch_bounds__(256) k1_proj(const float* __restrict__ query,
                                               const float* __restrict__ Wq) {
    int h = (blockIdx.x * blockDim.x + threadIdx.x) >> 5;  // 0..1023
    int lane = threadIdx.x & 31;
    const float4* w4 = (const float4*)(Wq + (size_t)h * QD);
    const float4* q4 = (const float4*)query;

    float acc[BB];
#pragma unroll
    for (int b = 0; b < BB; b++) acc[b] = 0.f;

#pragma unroll
    for (int i = 0; i < QD / 128; i++) {
        float4 w = w4[lane + i * 32];
#pragma unroll
        for (int b = 0; b < BB; b++) {
            float4 q = q4[b * (QD / 4) + lane + i * 32];
            acc[b] += w.x * q.x + w.y * q.y + w.z * q.z + w.w * q.w;
        }
    }
#pragma unroll
    for (int b = 0; b < BB; b++) {
#pragma unroll
        for (int o = 16; o; o >>= 1) acc[b] += __shfl_xor_sync(0xffffffffu, acc[b], o);
    }
    if (lane == 0) {
#pragma unroll
        for (int b = 0; b < BB; b++) g_q[b * HH + h] = acc[b];
    }
}

// ---------------------------------------------------------------------------
// K2: escore[b,s] = mask ? exp(sum_h w[h]*tanh(q[b,h]+pk[b,s,h])) : 0
// Warp per row. MASKED ROWS SKIP THE 4KB proj_key READ (~50% of rows).
// No max-subtraction needed: |score| <= ||w||_1 ~ 16 (clamped at 80).
// ---------------------------------------------------------------------------
__global__ void k2_scores(const float* __restrict__ pk, const float* __restrict__ w_energy,
                          const int* __restrict__ mask) {
    int row = (blockIdx.x * blockDim.x + threadIdx.x) >> 5;  // == b*SS + s
    int lane = threadIdx.x & 31;

    if (mask[row] == 0) {                 // broadcast load, all lanes same addr
        if (lane == 0) g_escore[row] = 0.f;
        return;
    }

    int b = row >> 12;  // / SS
    const float4* p4 = (const float4*)(pk + (size_t)row * HH);
    const float4* q4 = (const float4*)(g_q + (size_t)b * HH);
    const float4* w4 = (const float4*)w_energy;
    float acc = 0.f;
#pragma unroll
    for (int i = 0; i < HH / 128; i++) {
        float4 p = __ldcs(&p4[lane + i * 32]);
        float4 q = q4[lane + i * 32];
        float4 w = w4[lane + i * 32];
        acc += w.x * tanh_fast(q.x + p.x);
        acc += w.y * tanh_fast(q.y + p.y);
        acc += w.z * tanh_fast(q.z + p.z);
        acc += w.w * tanh_fast(q.w + p.w);
    }
#pragma unroll
    for (int o = 16; o; o >>= 1) acc += __shfl_xor_sync(0xffffffffu, acc, o);
    if (lane == 0)
        g_escore[row] = __expf(fminf(acc, 80.f));
}

// ---------------------------------------------------------------------------
// K4: unnormalized partial context with ZERO-ROW SKIP.
// Deterministic in-order compaction of active rows, then MLP-16 loop over the
// compacted list. blockIdx.x==0 block also emits the chunk's escore sum.
// grid = (KD/1024, BB, SSPLIT) = 1024 blocks.
// ---------------------------------------------------------------------------
__global__ void __launch_bounds__(256) k4_ctx(const float* __restrict__ value) {
    __shared__ float a[SCHUNK];
    __shared__ float sa[SCHUNK + 16];
    __shared__ short sidx[SCHUNK + 16];
    __shared__ int warpcnt[4];
    __shared__ int s_nact;
    int b = blockIdx.y;
    int ssec = blockIdx.z;
    int tid = threadIdx.x;
    int s0 = ssec * SCHUNK;

    if (tid < SCHUNK)
        a[tid] = g_escore[b * SS + s0 + tid];
    __syncthreads();

    // in-order compaction (tid order => deterministic)
    if (tid < SCHUNK) {
        bool act = (a[tid] != 0.f);
        unsigned m = __ballot_sync(0xffffffffu, act);
        int lane = tid & 31, w = tid >> 5;
        if (lane == 0) warpcnt[w] = __popc(m);
    }
    __syncthreads();
    if (tid < SCHUNK) {
        bool act = (a[tid] != 0.f);
        unsigned m = __ballot_sync(0xffffffffu, act);
        int lane = tid & 31, w = tid >> 5;
        int base = 0;
#pragma unroll
        for (int i = 0; i < 4; i++) if (i < w) base += warpcnt[i];
        int pos = base + __popc(m & ((1u << lane) - 1u));
        if (act) { sa[pos] = a[tid]; sidx[pos] = (short)tid; }
        if (tid == 0) {
            int n = warpcnt[0] + warpcnt[1] + warpcnt[2] + warpcnt[3];
            int npad = (n + 15) & ~15;
            for (int j = n; j < npad; j++) { sa[j] = 0.f; sidx[j] = 0; }
            s_nact = npad;
            if (blockIdx.x == 0) {                 // chunk sum, fixed order
                float t = 0.f;
                for (int s = 0; s < SCHUNK; s++) t += a[s];
                g_csum[b * SSPLIT + ssec] = t;
            }
        }
    }
    __syncthreads();
    int nact = s_nact;

    int k4i = blockIdx.x * blockDim.x + tid;
    const float4* vp = (const float4*)(value + ((size_t)b * SS + s0) * KD) + k4i;
    float4 acc = make_float4(0.f, 0.f, 0.f, 0.f);
    for (int j = 0; j < nact; j += 16) {
#pragma unroll
        for (int u = 0; u < 16; u++) {
            float al = sa[j + u];
            int s = sidx[j + u];
            float4 v = __ldcs(&vp[(size_t)s * (KD / 4)]);
            acc.x += al * v.x;
            acc.y += al * v.y;
            acc.z += al * v.z;
            acc.w += al * v.w;
        }
    }
    ((float4*)(g_partial + ((size_t)ssec * BB + b) * KD))[k4i] = acc;
}

// ---------------------------------------------------------------------------
// K_norm v5: 288 blocks x 512 threads.
//  blocks [0,32):   alphas = escore * inv   (1 float4/thread)
//  blocks [32,288): ctx — 32 items/block; 16 parts x 32 lanes; each part-warp
//                   covers 32 CONSECUTIVE k4i (coalesced), 2 planes/thread
//                   (fixed ssec order); smem combine in fixed part order.
// ---------------------------------------------------------------------------
__global__ void __launch_bounds__(512) k_norm(float* __restrict__ ctx,
                                              float* __restrict__ alphas) {
    int tid = threadIdx.x;
    if (blockIdx.x < 32) {
        int item = blockIdx.x * 512 + tid;      // 0 .. 16383 (float4 over escore)
        int b = item >> 10;                     // / (SS/4)
        float t = 0.f;
#pragma unroll
        for (int i = 0; i < SSPLIT; i++) t += g_csum[b * SSPLIT + i];  // fixed order
        float inv = 1.0f / t;
        float4 e = ((const float4*)g_escore)[item];
        e.x *= inv; e.y *= inv; e.z *= inv; e.w *= inv;
        ((float4*)alphas)[item] = e;
    } else {
        __shared__ float4 red[512];
        int cb = blockIdx.x - 32;               // 0..255
        int part = tid >> 5;                    // 0..15
        int local = tid & 31;                   // lane => consecutive k4i
        int ci = cb * 32 + local;               // global ctx float4 item
        int b = ci >> 9;                        // / (KD/4)
        int k4i = ci & (KD / 4 - 1);

        // 2 planes per thread, fixed ssec order
        const float4* p0 = (const float4*)(g_partial + ((size_t)(part * 2) * BB + b) * KD);
        const float4* p1 = (const float4*)(g_partial + ((size_t)(part * 2 + 1) * BB + b) * KD);
        float4 v0 = p0[k4i];
        float4 v1 = p1[k4i];
        red[tid] = make_float4(v0.x + v1.x, v0.y + v1.y, v0.z + v1.z, v0.w + v1.w);
        __syncthreads();
        if (part == 0) {
            float4 s = red[local];
#pragma unroll
            for (int p = 1; p < 16; p++) {      // fixed part order
                float4 v = red[p * 32 + local];
                s.x += v.x; s.y += v.y; s.z += v.z; s.w += v.w;
            }
            float t = 0.f;
#pragma unroll
            for (int i = 0; i < SSPLIT; i++) t += g_csum[b * SSPLIT + i];  // fixed order
            float inv = 1.0f / t;
            s.x *= inv; s.y *= inv; s.z *= inv; s.w *= inv;
            ((float4*)(ctx + (size_t)b * KD))[k4i] = s;
        }
    }
}

extern "C" void kernel_launch(void* const* d_in, const int* in_sizes, int n_in,
                              void* d_out, int out_size) {
    const int*   mask     = (const int*)d_in[0];
    const float* query    = (const float*)d_in[1];
    const float* proj_key = (const float*)d_in[2];
    const float* value    = (const float*)d_in[3];
    const float* Wq       = (const float*)d_in[4];
    const float* w_energy = (const float*)d_in[5];

    float* out    = (float*)d_out;
    float* ctx    = out;              // (B,1,K) = 32768 floats
    float* alphas = out + BB * KD;    // (B,1,S) = 65536 floats

    k1_proj<<<128, 256>>>(query, Wq);
    k2_scores<<<BB * SS / 8, 256>>>(proj_key, w_energy, mask);
    k4_ctx<<<dim3(KD / 1024, BB, SSPLIT), 256>>>(value);
    k_norm<<<288, 512>>>(ctx, alphas);
}

// round 16
// speedup vs baseline: 1.0553x; 1.0553x over previous
#include <cuda_runtime.h>

#define BB 16
#define SS 4096
#define HH 1024
#define QD 1024
#define KD 2048
#define SSPLIT 32
#define SCHUNK (SS / SSPLIT)   // 128

// Scratch (no allocation allowed anywhere)
__device__ float g_q[BB * HH];                 // 64 KB
__device__ float g_escore[BB * SS];            // 256 KB unnormalized exp(score)
__device__ float g_partial[SSPLIT * BB * KD];  // 4 MB unnormalized ctx partials
__device__ float g_csum[BB * SSPLIT];          // per-chunk escore sums

__device__ __forceinline__ float tanh_fast(float x) {
    float y;
    asm("tanh.approx.f32 %0, %1;" : "=f"(y) : "f"(x));
    return y;
}

// ---------------------------------------------------------------------------
// K1: q[b,h] = query[b,:]·Wq[h,:].  Warp per h-row, all 16 batches in regs.
// Wq read once (4 MB DRAM); query (64 KB) broadcast from L2. 1024 warps.
// ---------------------------------------------------------------------------
__global__ void __launch_bounds__(256) k1_proj(const float* __restrict__ query,
                                               const float* __restrict__ Wq) {
    int h = (blockIdx.x * blockDim.x + threadIdx.x) >> 5;  // 0..1023
    int lane = threadIdx.x & 31;
    const float4* w4 = (const float4*)(Wq + (size_t)h * QD);
    const float4* q4 = (const float4*)query;

    float acc[BB];
#pragma unroll
    for (int b = 0; b < BB; b++) acc[b] = 0.f;

#pragma unroll
    for (int i = 0; i < QD / 128; i++) {
        float4 w = w4[lane + i * 32];
#pragma unroll
        for (int b = 0; b < BB; b++) {
            float4 q = q4[b * (QD / 4) + lane + i * 32];
            acc[b] += w.x * q.x + w.y * q.y + w.z * q.z + w.w * q.w;
        }
    }
#pragma unroll
    for (int b = 0; b < BB; b++) {
#pragma unroll
        for (int o = 16; o; o >>= 1) acc[b] += __shfl_xor_sync(0xffffffffu, acc[b], o);
    }
    if (lane == 0) {
#pragma unroll
        for (int b = 0; b < BB; b++) g_q[b * HH + h] = acc[b];
    }
}

// ---------------------------------------------------------------------------
// K2: escore[b,s] = mask ? exp(sum_h w[h]*tanh(q[b,h]+pk[b,s,h])) : 0
// Warp per row. MASKED ROWS SKIP THE 4KB proj_key READ (~50% of rows).
// No max-subtraction needed: |score| <= ||w||_1 ~ 16 (clamped at 80).
// ---------------------------------------------------------------------------
__global__ void k2_scores(const float* __restrict__ pk, const float* __restrict__ w_energy,
                          const int* __restrict__ mask) {
    int row = (blockIdx.x * blockDim.x + threadIdx.x) >> 5;  // == b*SS + s
    int lane = threadIdx.x & 31;

    if (mask[row] == 0) {                 // broadcast load, all lanes same addr
        if (lane == 0) g_escore[row] = 0.f;
        return;
    }

    int b = row >> 12;  // / SS
    const float4* p4 = (const float4*)(pk + (size_t)row * HH);
    const float4* q4 = (const float4*)(g_q + (size_t)b * HH);
    const float4* w4 = (const float4*)w_energy;
    float acc = 0.f;
#pragma unroll
    for (int i = 0; i < HH / 128; i++) {
        float4 p = __ldcs(&p4[lane + i * 32]);
        float4 q = q4[lane + i * 32];
        float4 w = w4[lane + i * 32];
        acc += w.x * tanh_fast(q.x + p.x);
        acc += w.y * tanh_fast(q.y + p.y);
        acc += w.z * tanh_fast(q.z + p.z);
        acc += w.w * tanh_fast(q.w + p.w);
    }
#pragma unroll
    for (int o = 16; o; o >>= 1) acc += __shfl_xor_sync(0xffffffffu, acc, o);
    if (lane == 0)
        g_escore[row] = __expf(fminf(acc, 80.f));
}

// ---------------------------------------------------------------------------
// K4: unnormalized partial context with ZERO-ROW SKIP.
// Deterministic in-order compaction of active rows, then MLP-8 loop over the
// compacted list (8 in-flight float4 = register sweet spot, regs<=32).
// blockIdx.x==0 block also emits the chunk's escore sum.
// grid = (KD/1024, BB, SSPLIT) = 1024 blocks.
// ---------------------------------------------------------------------------
__global__ void __launch_bounds__(256) k4_ctx(const float* __restrict__ value) {
    __shared__ float a[SCHUNK];
    __shared__ float sa[SCHUNK + 8];
    __shared__ short sidx[SCHUNK + 8];
    __shared__ int warpcnt[4];
    __shared__ int s_nact;
    int b = blockIdx.y;
    int ssec = blockIdx.z;
    int tid = threadIdx.x;
    int s0 = ssec * SCHUNK;

    if (tid < SCHUNK)
        a[tid] = g_escore[b * SS + s0 + tid];
    __syncthreads();

    // in-order compaction (tid order => deterministic)
    if (tid < SCHUNK) {
        bool act = (a[tid] != 0.f);
        unsigned m = __ballot_sync(0xffffffffu, act);
        int lane = tid & 31, w = tid >> 5;
        if (lane == 0) warpcnt[w] = __popc(m);
    }
    __syncthreads();
    if (tid < SCHUNK) {
        bool act = (a[tid] != 0.f);
        unsigned m = __ballot_sync(0xffffffffu, act);
        int lane = tid & 31, w = tid >> 5;
        int base = 0;
#pragma unroll
        for (int i = 0; i < 4; i++) if (i < w) base += warpcnt[i];
        int pos = base + __popc(m & ((1u << lane) - 1u));
        if (act) { sa[pos] = a[tid]; sidx[pos] = (short)tid; }
        if (tid == 0) {
            int n = warpcnt[0] + warpcnt[1] + warpcnt[2] + warpcnt[3];
            int npad = (n + 7) & ~7;
            for (int j = n; j < npad; j++) { sa[j] = 0.f; sidx[j] = 0; }
            s_nact = npad;
            if (blockIdx.x == 0) {                 // chunk sum, fixed order
                float t = 0.f;
                for (int s = 0; s < SCHUNK; s++) t += a[s];
                g_csum[b * SSPLIT + ssec] = t;
            }
        }
    }
    __syncthreads();
    int nact = s_nact;

    int k4i = blockIdx.x * blockDim.x + tid;
    const float4* vp = (const float4*)(value + ((size_t)b * SS + s0) * KD) + k4i;
    float4 acc = make_float4(0.f, 0.f, 0.f, 0.f);
    for (int j = 0; j < nact; j += 8) {
#pragma unroll
        for (int u = 0; u < 8; u++) {
            float al = sa[j + u];
            int s = sidx[j + u];
            float4 v = __ldcs(&vp[(size_t)s * (KD / 4)]);
            acc.x += al * v.x;
            acc.y += al * v.y;
            acc.z += al * v.z;
            acc.w += al * v.w;
        }
    }
    ((float4*)(g_partial + ((size_t)ssec * BB + b) * KD))[k4i] = acc;
}

// ---------------------------------------------------------------------------
// K_norm v4: 320 blocks, warp-coalesced (measured floor ~5.6us).
//  blocks [0,64):   alphas = escore * inv   (1 float4/thread)
//  blocks [64,320): ctx — 32 items/block; 8 parts x 32 lanes; each part-warp
//                   covers 32 CONSECUTIVE k4i (coalesced) and sums 4 partials
//                   (fixed ssec order); smem combine in fixed part order.
// ---------------------------------------------------------------------------
__global__ void __launch_bounds__(256) k_norm(float* __restrict__ ctx,
                                              float* __restrict__ alphas) {
    int tid = threadIdx.x;
    if (blockIdx.x < 64) {
        int item = blockIdx.x * 256 + tid;      // 0 .. 16383 (float4 over escore)
        int b = item >> 10;                     // / (SS/4)
        float t = 0.f;
#pragma unroll
        for (int i = 0; i < SSPLIT; i++) t += g_csum[b * SSPLIT + i];  // fixed order
        float inv = 1.0f / t;
        float4 e = ((const float4*)g_escore)[item];
        e.x *= inv; e.y *= inv; e.z *= inv; e.w *= inv;
        ((float4*)alphas)[item] = e;
    } else {
        __shared__ float4 red[256];
        int cb = blockIdx.x - 64;               // 0..255
        int part = tid >> 5;                    // 0..7
        int local = tid & 31;                   // lane => consecutive k4i
        int ci = cb * 32 + local;               // global ctx float4 item
        int b = ci >> 9;                        // / (KD/4)
        int k4i = ci & (KD / 4 - 1);

        float4 acc = make_float4(0.f, 0.f, 0.f, 0.f);
#pragma unroll
        for (int j = 0; j < 4; j++) {           // fixed ssec order within part
            int ssec = part * 4 + j;
            float4 v = ((const float4*)(g_partial + ((size_t)ssec * BB + b) * KD))[k4i];
            acc.x += v.x; acc.y += v.y; acc.z += v.z; acc.w += v.w;
        }
        red[tid] = acc;
        __syncthreads();
        if (part == 0) {
            float4 s = red[local];
#pragma unroll
            for (int p = 1; p < 8; p++) {       // fixed part order
                float4 v = red[p * 32 + local];
                s.x += v.x; s.y += v.y; s.z += v.z; s.w += v.w;
            }
            float t = 0.f;
#pragma unroll
            for (int i = 0; i < SSPLIT; i++) t += g_csum[b * SSPLIT + i];  // fixed order
            float inv = 1.0f / t;
            s.x *= inv; s.y *= inv; s.z *= inv; s.w *= inv;
            ((float4*)(ctx + (size_t)b * KD))[k4i] = s;
        }
    }
}

extern "C" void kernel_launch(void* const* d_in, const int* in_sizes, int n_in,
                              void* d_out, int out_size) {
    const int*   mask     = (const int*)d_in[0];
    const float* query    = (const float*)d_in[1];
    const float* proj_key = (const float*)d_in[2];
    const float* value    = (const float*)d_in[3];
    const float* Wq       = (const float*)d_in[4];
    const float* w_energy = (const float*)d_in[5];

    float* out    = (float*)d_out;
    float* ctx    = out;              // (B,1,K) = 32768 floats
    float* alphas = out + BB * KD;    // (B,1,S) = 65536 floats

    k1_proj<<<128, 256>>>(query, Wq);
    k2_scores<<<BB * SS / 8, 256>>>(proj_key, w_energy, mask);
    k4_ctx<<<dim3(KD / 1024, BB, SSPLIT), 256>>>(value);
    k_norm<<<320, 256>>>(ctx, alphas);
}

// round 17
// speedup vs baseline: 1.0816x; 1.0249x over previous
#include <cuda_runtime.h>

#define BB 16
#define SS 4096
#define HH 1024
#define QD 1024
#define KD 2048
#define SSPLIT 32
#define SCHUNK (SS / SSPLIT)   // 128

// Scratch (no allocation allowed anywhere)
__device__ float g_q[BB * HH];                 // 64 KB
__device__ float g_escore[BB * SS];            // 256 KB unnormalized exp(score)
__device__ float g_partial[SSPLIT * BB * KD];  // 4 MB unnormalized ctx partials
__device__ float g_csum[BB * SSPLIT];          // per-chunk escore sums

__device__ __forceinline__ float tanh_fast(float x) {
    float y;
    asm("tanh.approx.f32 %0, %1;" : "=f"(y) : "f"(x));
    return y;
}

// ---------------------------------------------------------------------------
// K1: q[b,h] = query[b,:]·Wq[h,:].  Warp per h-row, all 16 batches in regs.
// Wq read once (4 MB DRAM); query (64 KB) broadcast from L2. 1024 warps.
// ---------------------------------------------------------------------------
__global__ void __launch_bounds__(256) k1_proj(const float* __restrict__ query,
                                               const float* __restrict__ Wq) {
    int h = (blockIdx.x * blockDim.x + threadIdx.x) >> 5;  // 0..1023
    int lane = threadIdx.x & 31;
    const float4* w4 = (const float4*)(Wq + (size_t)h * QD);
    const float4* q4 = (const float4*)query;

    float acc[BB];
#pragma unroll
    for (int b = 0; b < BB; b++) acc[b] = 0.f;

#pragma unroll
    for (int i = 0; i < QD / 128; i++) {
        float4 w = w4[lane + i * 32];
#pragma unroll
        for (int b = 0; b < BB; b++) {
            float4 q = q4[b * (QD / 4) + lane + i * 32];
            acc[b] += w.x * q.x + w.y * q.y + w.z * q.z + w.w * q.w;
        }
    }
#pragma unroll
    for (int b = 0; b < BB; b++) {
#pragma unroll
        for (int o = 16; o; o >>= 1) acc[b] += __shfl_xor_sync(0xffffffffu, acc[b], o);
    }
    if (lane == 0) {
#pragma unroll
        for (int b = 0; b < BB; b++) g_q[b * HH + h] = acc[b];
    }
}

// ---------------------------------------------------------------------------
// K2: escore[b,s] = mask ? exp(sum_h w[h]*tanh(q[b,h]+pk[b,s,h])) : 0
// Warp per row. MASKED ROWS SKIP THE 4KB proj_key READ (~50% of rows).
// No max-subtraction needed: |score| <= ||w||_1 ~ 16 (clamped at 80).
// ---------------------------------------------------------------------------
__global__ void k2_scores(const float* __restrict__ pk, const float* __restrict__ w_energy,
                          const int* __restrict__ mask) {
    int row = (blockIdx.x * blockDim.x + threadIdx.x) >> 5;  // == b*SS + s
    int lane = threadIdx.x & 31;

    if (mask[row] == 0) {                 // broadcast load, all lanes same addr
        if (lane == 0) g_escore[row] = 0.f;
        return;
    }

    int b = row >> 12;  // / SS
    const float4* p4 = (const float4*)(pk + (size_t)row * HH);
    const float4* q4 = (const float4*)(g_q + (size_t)b * HH);
    const float4* w4 = (const float4*)w_energy;
    float acc = 0.f;
#pragma unroll
    for (int i = 0; i < HH / 128; i++) {
        float4 p = __ldcs(&p4[lane + i * 32]);
        float4 q = q4[lane + i * 32];
        float4 w = w4[lane + i * 32];
        acc += w.x * tanh_fast(q.x + p.x);
        acc += w.y * tanh_fast(q.y + p.y);
        acc += w.z * tanh_fast(q.z + p.z);
        acc += w.w * tanh_fast(q.w + p.w);
    }
#pragma unroll
    for (int o = 16; o; o >>= 1) acc += __shfl_xor_sync(0xffffffffu, acc, o);
    if (lane == 0)
        g_escore[row] = __expf(fminf(acc, 80.f));
}

// ---------------------------------------------------------------------------
// K4: unnormalized partial context with ZERO-ROW SKIP.
// ONE 512-thread block per (b, ssec) chunk covers the FULL 2048-col row:
// compaction + csum done once per chunk, each active row read as one
// contiguous 8 KB span. Deterministic in-order compaction; MLP-8 loop.
// grid = (BB, SSPLIT) = 512 blocks x 512 threads.
// ---------------------------------------------------------------------------
__global__ void __launch_bounds__(512) k4_ctx(const float* __restrict__ value) {
    __shared__ float a[SCHUNK];
    __shared__ float sa[SCHUNK + 8];
    __shared__ short sidx[SCHUNK + 8];
    __shared__ int warpcnt[4];
    __shared__ int s_nact;
    int b = blockIdx.x;
    int ssec = blockIdx.y;
    int tid = threadIdx.x;
    int s0 = ssec * SCHUNK;

    if (tid < SCHUNK)
        a[tid] = g_escore[b * SS + s0 + tid];
    __syncthreads();

    // in-order compaction (tid order => deterministic), first 4 warps
    if (tid < SCHUNK) {
        bool act = (a[tid] != 0.f);
        unsigned m = __ballot_sync(0xffffffffu, act);
        int lane = tid & 31, w = tid >> 5;
        if (lane == 0) warpcnt[w] = __popc(m);
    }
    __syncthreads();
    if (tid < SCHUNK) {
        bool act = (a[tid] != 0.f);
        unsigned m = __ballot_sync(0xffffffffu, act);
        int lane = tid & 31, w = tid >> 5;
        int base = 0;
#pragma unroll
        for (int i = 0; i < 4; i++) if (i < w) base += warpcnt[i];
        int pos = base + __popc(m & ((1u << lane) - 1u));
        if (act) { sa[pos] = a[tid]; sidx[pos] = (short)tid; }
        if (tid == 0) {
            int n = warpcnt[0] + warpcnt[1] + warpcnt[2] + warpcnt[3];
            int npad = (n + 7) & ~7;
            for (int j = n; j < npad; j++) { sa[j] = 0.f; sidx[j] = 0; }
            s_nact = npad;
            float t = 0.f;                        // chunk sum, fixed order
            for (int s = 0; s < SCHUNK; s++) t += a[s];
            g_csum[b * SSPLIT + ssec] = t;
        }
    }
    __syncthreads();
    int nact = s_nact;

    int k4i = tid;                                // 512 float4 = full 2048-col row
    const float4* vp = (const float4*)(value + ((size_t)b * SS + s0) * KD) + k4i;
    float4 acc = make_float4(0.f, 0.f, 0.f, 0.f);
    for (int j = 0; j < nact; j += 8) {
#pragma unroll
        for (int u = 0; u < 8; u++) {
            float al = sa[j + u];
            int s = sidx[j + u];
            float4 v = __ldcs(&vp[(size_t)s * (KD / 4)]);
            acc.x += al * v.x;
            acc.y += al * v.y;
            acc.z += al * v.z;
            acc.w += al * v.w;
        }
    }
    ((float4*)(g_partial + ((size_t)ssec * BB + b) * KD))[k4i] = acc;
}

// ---------------------------------------------------------------------------
// K_norm v4: 320 blocks, warp-coalesced (measured floor ~5.6us).
//  blocks [0,64):   alphas = escore * inv   (1 float4/thread)
//  blocks [64,320): ctx — 32 items/block; 8 parts x 32 lanes; each part-warp
//                   covers 32 CONSECUTIVE k4i (coalesced) and sums 4 partials
//                   (fixed ssec order); smem combine in fixed part order.
// ---------------------------------------------------------------------------
__global__ void __launch_bounds__(256) k_norm(float* __restrict__ ctx,
                                              float* __restrict__ alphas) {
    int tid = threadIdx.x;
    if (blockIdx.x < 64) {
        int item = blockIdx.x * 256 + tid;      // 0 .. 16383 (float4 over escore)
        int b = item >> 10;                     // / (SS/4)
        float t = 0.f;
#pragma unroll
        for (int i = 0; i < SSPLIT; i++) t += g_csum[b * SSPLIT + i];  // fixed order
        float inv = 1.0f / t;
        float4 e = ((const float4*)g_escore)[item];
        e.x *= inv; e.y *= inv; e.z *= inv; e.w *= inv;
        ((float4*)alphas)[item] = e;
    } else {
        __shared__ float4 red[256];
        int cb = blockIdx.x - 64;               // 0..255
        int part = tid >> 5;                    // 0..7
        int local = tid & 31;                   // lane => consecutive k4i
        int ci = cb * 32 + local;               // global ctx float4 item
        int b = ci >> 9;                        // / (KD/4)
        int k4i = ci & (KD / 4 - 1);

        float4 acc = make_float4(0.f, 0.f, 0.f, 0.f);
#pragma unroll
        for (int j = 0; j < 4; j++) {           // fixed ssec order within part
            int ssec = part * 4 + j;
            float4 v = ((const float4*)(g_partial + ((size_t)ssec * BB + b) * KD))[k4i];
            acc.x += v.x; acc.y += v.y; acc.z += v.z; acc.w += v.w;
        }
        red[tid] = acc;
        __syncthreads();
        if (part == 0) {
            float4 s = red[local];
#pragma unroll
            for (int p = 1; p < 8; p++) {       // fixed part order
                float4 v = red[p * 32 + local];
                s.x += v.x; s.y += v.y; s.z += v.z; s.w += v.w;
            }
            float t = 0.f;
#pragma unroll
            for (int i = 0; i < SSPLIT; i++) t += g_csum[b * SSPLIT + i];  // fixed order
            float inv = 1.0f / t;
            s.x *= inv; s.y *= inv; s.z *= inv; s.w *= inv;
            ((float4*)(ctx + (size_t)b * KD))[k4i] = s;
        }
    }
}

extern "C" void kernel_launch(void* const* d_in, const int* in_sizes, int n_in,
                              void* d_out, int out_size) {
    const int*   mask     = (const int*)d_in[0];
    const float* query    = (const float*)d_in[1];
    const float* proj_key = (const float*)d_in[2];
    const float* value    = (const float*)d_in[3];
    const float* Wq       = (const float*)d_in[4];
    const float* w_energy = (const float*)d_in[5];

    float* out    = (float*)d_out;
    float* ctx    = out;              // (B,1,K) = 32768 floats
    float* alphas = out + BB * KD;    // (B,1,S) = 65536 floats

    k1_proj<<<128, 256>>>(query, Wq);
    k2_scores<<<BB * SS / 8, 256>>>(proj_key, w_energy, mask);
    k4_ctx<<<dim3(BB, SSPLIT), 512>>>(value);
    k_norm<<<320, 256>>>(ctx, alphas);
}